// round 1
// baseline (speedup 1.0000x reference)
#include <cuda_runtime.h>
#include <math.h>

#define N_TOK   4096
#define H_DIM   128
#define NH      8
#define HD      16
#define FF_DIM  256
#define L_LAYER 4
#define LAT_DIM 16

// ---------------- scratch (static device globals; no runtime alloc) ----------------
__device__ float g_x   [N_TOK * H_DIM];    // residual stream
__device__ float g_xn  [N_TOK * H_DIM];    // LN output / lat hidden
__device__ float g_qkv [N_TOK * 3 * H_DIM];
__device__ float g_attn[N_TOK * H_DIM];
__device__ float g_tmp [N_TOK * FF_DIM];   // FF hidden / beta hidden
__device__ float g_eta [N_TOK];
__device__ float g_phi [N_TOK];
__device__ float g_lat [N_TOK * LAT_DIM];
__device__ float g_beta[N_TOK];

// ---------------- eta/phi precompute ----------------
__global__ void etaphi_kernel(const float* __restrict__ x_raw) {
    int i = blockIdx.x * blockDim.x + threadIdx.x;
    if (i >= N_TOK) return;
    g_eta[i] = x_raw[i * 16 + 1] * 5.24f   + (-2.62f);
    g_phi[i] = x_raw[i * 16 + 2] * 6.2832f + (-3.1416f);
}

// ---------------- generic tiled GEMM: C = A(NxK) @ W(MxK)^T + bias (+res) (relu?) ----
#define BM 32
#define BN 64
#define BK 32

__global__ __launch_bounds__(256)
void gemm_kernel(const float* __restrict__ A, const float* __restrict__ W,
                 const float* __restrict__ bias, const float* __restrict__ res,
                 float* __restrict__ C, int N, int M, int K, int relu) {
    __shared__ float As[BM][BK + 1];
    __shared__ float Ws[BN][BK + 1];

    const int tid  = threadIdx.x;
    const int tx   = tid & 31;
    const int ty   = tid >> 5;
    const int row0 = blockIdx.x * BM;
    const int col0 = blockIdx.y * BN;

    float acc[4][2] = {{0.f,0.f},{0.f,0.f},{0.f,0.f},{0.f,0.f}};

    for (int k0 = 0; k0 < K; k0 += BK) {
        #pragma unroll
        for (int t = 0; t < 4; t++) {
            int e = tid + t * 256;
            int r = e >> 5, c = e & 31;
            int gr = row0 + r, gk = k0 + c;
            As[r][c] = (gr < N && gk < K) ? A[gr * K + gk] : 0.f;
        }
        #pragma unroll
        for (int t = 0; t < 8; t++) {
            int e = tid + t * 256;
            int r = e >> 5, c = e & 31;
            int gm = col0 + r, gk = k0 + c;
            Ws[r][c] = (gm < M && gk < K) ? W[gm * K + gk] : 0.f;
        }
        __syncthreads();
        #pragma unroll
        for (int kk = 0; kk < BK; kk++) {
            float a0 = As[ty     ][kk];
            float a1 = As[ty +  8][kk];
            float a2 = As[ty + 16][kk];
            float a3 = As[ty + 24][kk];
            float w0 = Ws[tx     ][kk];
            float w1 = Ws[tx + 32][kk];
            acc[0][0] += a0 * w0;  acc[0][1] += a0 * w1;
            acc[1][0] += a1 * w0;  acc[1][1] += a1 * w1;
            acc[2][0] += a2 * w0;  acc[2][1] += a2 * w1;
            acc[3][0] += a3 * w0;  acc[3][1] += a3 * w1;
        }
        __syncthreads();
    }

    #pragma unroll
    for (int i = 0; i < 4; i++) {
        int gr = row0 + ty + i * 8;
        if (gr >= N) continue;
        #pragma unroll
        for (int j = 0; j < 2; j++) {
            int gm = col0 + tx + j * 32;
            if (gm >= M) continue;
            float v = acc[i][j] + bias[gm];
            if (res)  v += res[gr * M + gm];
            if (relu) v = fmaxf(v, 0.f);
            C[gr * M + gm] = v;
        }
    }
}

// ---------------- LayerNorm: one row per block (128 threads) ----------------
__global__ __launch_bounds__(128)
void ln_kernel(const float* __restrict__ x, const float* __restrict__ sc,
               const float* __restrict__ bi, float* __restrict__ out) {
    const int row = blockIdx.x;
    const int t   = threadIdx.x;
    float v = x[row * H_DIM + t];

    __shared__ float sh1[4], sh2[4];
    float s = v;
    #pragma unroll
    for (int o = 16; o; o >>= 1) s += __shfl_xor_sync(0xffffffffu, s, o);
    if ((t & 31) == 0) sh1[t >> 5] = s;
    __syncthreads();
    float mean = (sh1[0] + sh1[1] + sh1[2] + sh1[3]) * (1.f / 128.f);

    float d = v - mean;
    float q = d * d;
    #pragma unroll
    for (int o = 16; o; o >>= 1) q += __shfl_xor_sync(0xffffffffu, q, o);
    if ((t & 31) == 0) sh2[t >> 5] = q;
    __syncthreads();
    float var = (sh2[0] + sh2[1] + sh2[2] + sh2[3]) * (1.f / 128.f);

    out[row * H_DIM + t] = d * rsqrtf(var + 1e-5f) * sc[t] + bi[t];
}

// ---------------- fused attention with on-the-fly dR mask --------------------
// grid: (N/64, NH), block 256. Thread = 1 q-row x 16 interleaved key columns.
#define QT 64
#define KT 64
#define NEG (-1e30f)

__global__ __launch_bounds__(256)
void attn_kernel(const float* __restrict__ qkv, float* __restrict__ o) {
    __shared__ float Ks[KT][HD + 1];
    __shared__ float Vs[KT][HD + 1];
    __shared__ float ek[KT], pk[KT];

    const int q0   = blockIdx.x * QT;
    const int h    = blockIdx.y;
    const int tid  = threadIdx.x;
    const int r    = tid >> 2;     // q row within tile
    const int cgrp = tid & 3;      // key column interleave group
    const int qrow = q0 + r;

    float qv[HD];
    #pragma unroll
    for (int d = 0; d < HD; d++) qv[d] = qkv[qrow * 384 + h * HD + d];
    const float eq = g_eta[qrow];
    const float pq = g_phi[qrow];

    float m = NEG, lsum = 0.f;
    float acc[HD];
    #pragma unroll
    for (int d = 0; d < HD; d++) acc[d] = 0.f;

    for (int k0 = 0; k0 < N_TOK; k0 += KT) {
        #pragma unroll
        for (int t = 0; t < 4; t++) {
            int e = tid + t * 256;
            int kk = e >> 4, d = e & 15;
            Ks[kk][d] = qkv[(k0 + kk) * 384 + 128 + h * HD + d];
            Vs[kk][d] = qkv[(k0 + kk) * 384 + 256 + h * HD + d];
        }
        if (tid < KT) { ek[tid] = g_eta[k0 + tid]; pk[tid] = g_phi[k0 + tid]; }
        __syncthreads();

        float p[16];
        float tmax = NEG;
        #pragma unroll
        for (int j = 0; j < 16; j++) {
            int c = (j << 2) | cgrp;
            float sv = 0.f;
            #pragma unroll
            for (int d = 0; d < HD; d++) sv += qv[d] * Ks[c][d];
            float de = eq - ek[c];
            float dp = pq - pk[c];
            dp -= 6.28318530718f * rintf(dp * 0.159154943092f);
            float dr2 = de * de + dp * dp;
            sv = (dr2 <= 0.04f) ? sv * 0.25f : NEG;
            p[j] = sv;
            tmax = fmaxf(tmax, sv);
        }
        tmax = fmaxf(tmax, __shfl_xor_sync(0xffffffffu, tmax, 1));
        tmax = fmaxf(tmax, __shfl_xor_sync(0xffffffffu, tmax, 2));
        float mnew = fmaxf(m, tmax);
        float factor = __expf(m - mnew);

        float psum = 0.f;
        #pragma unroll
        for (int j = 0; j < 16; j++) {
            p[j] = __expf(p[j] - mnew);
            psum += p[j];
        }
        psum += __shfl_xor_sync(0xffffffffu, psum, 1);
        psum += __shfl_xor_sync(0xffffffffu, psum, 2);
        lsum = lsum * factor + psum;

        #pragma unroll
        for (int d = 0; d < HD; d++) {
            float a = acc[d] * factor;
            #pragma unroll
            for (int j = 0; j < 16; j++) {
                int c = (j << 2) | cgrp;
                a += p[j] * Vs[c][d];
            }
            acc[d] = a;
        }
        m = mnew;
        __syncthreads();
    }

    // reduce accumulators across the 4 threads of this q-row
    #pragma unroll
    for (int d = 0; d < HD; d++) {
        acc[d] += __shfl_xor_sync(0xffffffffu, acc[d], 1);
        acc[d] += __shfl_xor_sync(0xffffffffu, acc[d], 2);
    }
    float inv = 1.f / lsum;
    #pragma unroll
    for (int dd = 0; dd < 4; dd++) {
        int d = cgrp * 4 + dd;
        o[qrow * H_DIM + h * HD + d] = acc[d] * inv;
    }
}

// ---------------- heads epilogue ----------------
__global__ void final_kernel(float* __restrict__ out) {
    int i = blockIdx.x * blockDim.x + threadIdx.x;
    if (i >= N_TOK) return;
    float bb = 1.f / (1.f + __expf(-g_beta[i]));
    bb = fminf(fmaxf(bb, 1e-6f), 1.f - 1e-6f);
    out[i] = bb;
    float nn = 0.f;
    float l[LAT_DIM];
    #pragma unroll
    for (int d = 0; d < LAT_DIM; d++) { l[d] = g_lat[i * LAT_DIM + d]; nn += l[d] * l[d]; }
    float inv = 1.f / fmaxf(sqrtf(nn), 1e-12f);
    #pragma unroll
    for (int d = 0; d < LAT_DIM; d++) out[N_TOK + i * LAT_DIM + d] = l[d] * inv;
}

// ---------------- host orchestration ----------------
static inline float* dptr(void* p) { return (float*)p; }

extern "C" void kernel_launch(void* const* d_in, const int* in_sizes, int n_in,
                              void* d_out, int out_size) {
    const float* x_raw  = (const float*)d_in[0];
    // d_in[1] = batch (unused)
    const float* in_w   = (const float*)d_in[2];
    const float* in_b   = (const float*)d_in[3];
    const float* ln1_s  = (const float*)d_in[4];
    const float* ln1_b  = (const float*)d_in[5];
    const float* qkv_w  = (const float*)d_in[6];
    const float* qkv_b  = (const float*)d_in[7];
    const float* ao_w   = (const float*)d_in[8];
    const float* ao_b   = (const float*)d_in[9];
    const float* ln2_s  = (const float*)d_in[10];
    const float* ln2_b  = (const float*)d_in[11];
    const float* f1_w   = (const float*)d_in[12];
    const float* f1_b   = (const float*)d_in[13];
    const float* f2_w   = (const float*)d_in[14];
    const float* f2_b   = (const float*)d_in[15];
    const float* lat1_w = (const float*)d_in[16];
    const float* lat1_b = (const float*)d_in[17];
    const float* lat2_w = (const float*)d_in[18];
    const float* lat2_b = (const float*)d_in[19];
    const float* b1_w   = (const float*)d_in[20];
    const float* b1_b   = (const float*)d_in[21];
    const float* b2_w   = (const float*)d_in[22];
    const float* b2_b   = (const float*)d_in[23];

    float *x, *xn, *qkv, *attn, *tmp, *lat, *beta;
    cudaGetSymbolAddress((void**)&x,    g_x);
    cudaGetSymbolAddress((void**)&xn,   g_xn);
    cudaGetSymbolAddress((void**)&qkv,  g_qkv);
    cudaGetSymbolAddress((void**)&attn, g_attn);
    cudaGetSymbolAddress((void**)&tmp,  g_tmp);
    cudaGetSymbolAddress((void**)&lat,  g_lat);
    cudaGetSymbolAddress((void**)&beta, g_beta);

    dim3 blk(256);

    // eta/phi
    etaphi_kernel<<<(N_TOK + 255) / 256, 256>>>(x_raw);

    // input projection: x = x_raw @ in_w^T + in_b   (K=16, M=128)
    gemm_kernel<<<dim3(N_TOK / BM, (H_DIM + BN - 1) / BN), blk>>>(
        x_raw, in_w, in_b, nullptr, x, N_TOK, H_DIM, 16, 0);

    for (int l = 0; l < L_LAYER; l++) {
        // LN1
        ln_kernel<<<N_TOK, 128>>>(x, ln1_s + l * H_DIM, ln1_b + l * H_DIM, xn);
        // QKV: [N,128] @ [384,128]^T
        gemm_kernel<<<dim3(N_TOK / BM, (3 * H_DIM) / BN), blk>>>(
            xn, qkv_w + (size_t)l * 3 * H_DIM * H_DIM, qkv_b + l * 3 * H_DIM,
            nullptr, qkv, N_TOK, 3 * H_DIM, H_DIM, 0);
        // attention (mask on the fly)
        attn_kernel<<<dim3(N_TOK / QT, NH), blk>>>(qkv, attn);
        // attn out proj + residual into x
        gemm_kernel<<<dim3(N_TOK / BM, H_DIM / BN), blk>>>(
            attn, ao_w + (size_t)l * H_DIM * H_DIM, ao_b + l * H_DIM,
            x, x, N_TOK, H_DIM, H_DIM, 0);
        // LN2
        ln_kernel<<<N_TOK, 128>>>(x, ln2_s + l * H_DIM, ln2_b + l * H_DIM, xn);
        // FF1 (ReLU): [N,128] @ [256,128]^T
        gemm_kernel<<<dim3(N_TOK / BM, FF_DIM / BN), blk>>>(
            xn, f1_w + (size_t)l * FF_DIM * H_DIM, f1_b + l * FF_DIM,
            nullptr, tmp, N_TOK, FF_DIM, H_DIM, 1);
        // FF2 + residual: [N,256] @ [128,256]^T
        gemm_kernel<<<dim3(N_TOK / BM, H_DIM / BN), blk>>>(
            tmp, f2_w + (size_t)l * H_DIM * FF_DIM, f2_b + l * H_DIM,
            x, x, N_TOK, H_DIM, FF_DIM, 0);
    }

    // lat head: relu(x @ lat1^T) @ lat2^T
    gemm_kernel<<<dim3(N_TOK / BM, H_DIM / BN), blk>>>(
        x, lat1_w, lat1_b, nullptr, xn, N_TOK, H_DIM, H_DIM, 1);
    gemm_kernel<<<dim3(N_TOK / BM, 1), blk>>>(
        xn, lat2_w, lat2_b, nullptr, lat, N_TOK, LAT_DIM, H_DIM, 0);

    // beta head: sigmoid(relu(x @ b1^T) @ b2^T)
    gemm_kernel<<<dim3(N_TOK / BM, 1), blk>>>(
        x, b1_w, b1_b, nullptr, tmp, N_TOK, H_DIM / 2, H_DIM, 1);
    gemm_kernel<<<dim3(N_TOK / BM, 1), blk>>>(
        tmp, b2_w, b2_b, nullptr, beta, N_TOK, 1, H_DIM / 2, 0);

    final_kernel<<<(N_TOK + 255) / 256, 256>>>((float*)d_out);
}

// round 3
// speedup vs baseline: 6.4060x; 6.4060x over previous
#include <cuda_runtime.h>
#include <math.h>

#define N_TOK   4096
#define H_DIM   128
#define NH      8
#define HD      16
#define FF_DIM  256
#define L_LAYER 4
#define LAT_DIM 16
#define CAP     128

// ---------------- scratch (static device globals; no runtime alloc) ----------------
__device__ __align__(256) float g_x   [N_TOK * H_DIM];
__device__ __align__(256) float g_xn  [N_TOK * H_DIM];
__device__ __align__(256) float g_qkv [N_TOK * 3 * H_DIM];
__device__ __align__(256) float g_attn[N_TOK * H_DIM];
__device__ __align__(256) float g_tmp [N_TOK * FF_DIM];
__device__ __align__(256) float g_eta [N_TOK];
__device__ __align__(256) float g_phi [N_TOK];
__device__ __align__(256) float g_lat [N_TOK * LAT_DIM];
__device__ __align__(256) float g_beta[N_TOK];
__device__ __align__(256) int   g_nbr [N_TOK * CAP];
__device__ __align__(256) int   g_ncnt[N_TOK];

// ---------------- eta/phi precompute ----------------
__global__ void etaphi_kernel(const float* __restrict__ x_raw) {
    int i = blockIdx.x * blockDim.x + threadIdx.x;
    if (i >= N_TOK) return;
    g_eta[i] = x_raw[i * 16 + 1] * 5.24f   + (-2.62f);
    g_phi[i] = x_raw[i * 16 + 2] * 6.2832f + (-3.1416f);
}

// ---------------- neighbor list build: one warp per query ----------------
__global__ __launch_bounds__(256)
void nbr_kernel() {
    int warp = (blockIdx.x * blockDim.x + threadIdx.x) >> 5;
    int lane = threadIdx.x & 31;
    if (warp >= N_TOK) return;
    float eq = g_eta[warp], pq = g_phi[warp];
    int cnt = 0;
    for (int k = lane; k < N_TOK; k += 32) {
        float de = eq - g_eta[k];
        float dp = pq - g_phi[k];
        dp -= 6.28318530718f * rintf(dp * 0.159154943092f);
        bool hit = (de * de + dp * dp) <= 0.04f;
        unsigned mask = __ballot_sync(0xffffffffu, hit);
        if (hit) {
            int off = cnt + __popc(mask & ((1u << lane) - 1u));
            if (off < CAP) g_nbr[warp * CAP + off] = k;
        }
        cnt += __popc(mask);
    }
    if (lane == 0) g_ncnt[warp] = min(cnt, CAP);
}

// ---------------- register-tiled GEMM: C = A(NxK) @ W(MxK)^T + bias (+res)(relu?) ---
// BM=64, BN=64, BK=16, 128 threads, 8x4 outputs per thread.
#define GM 64
#define GN 64
#define GK 16
#define GMP 68   // row pad: 68 floats = 272B, 16B multiple -> aligned LDS.128 any k

__global__ __launch_bounds__(128)
void gemm2_kernel(const float* __restrict__ A, const float* __restrict__ W,
                  const float* __restrict__ bias, const float* __restrict__ res,
                  float* __restrict__ C, int N, int M, int K, int relu) {
    __shared__ __align__(16) float As[GK][GMP];
    __shared__ __align__(16) float Ws[GK][GMP];

    const int tid  = threadIdx.x;
    const int row0 = blockIdx.x * GM;
    const int col0 = blockIdx.y * GN;
    const int tx   = tid & 15;   // n: 4 cols each
    const int ty   = tid >> 4;   // m: 8 rows each

    float acc[8][4];
    #pragma unroll
    for (int i = 0; i < 8; i++)
        #pragma unroll
        for (int j = 0; j < 4; j++) acc[i][j] = 0.f;

    for (int k0 = 0; k0 < K; k0 += GK) {
        #pragma unroll
        for (int t = 0; t < 2; t++) {
            int i = tid + t * 128;            // 0..255
            int r = i >> 2, kq = (i & 3) << 2;
            int gr = row0 + r;
            float4 v = make_float4(0.f, 0.f, 0.f, 0.f);
            if (gr < N) v = *(const float4*)(A + (size_t)gr * K + k0 + kq);
            As[kq + 0][r] = v.x; As[kq + 1][r] = v.y;
            As[kq + 2][r] = v.z; As[kq + 3][r] = v.w;
        }
        #pragma unroll
        for (int t = 0; t < 2; t++) {
            int i = tid + t * 128;
            int r = i >> 2, kq = (i & 3) << 2;
            int gm = col0 + r;
            float4 v = make_float4(0.f, 0.f, 0.f, 0.f);
            if (gm < M) v = *(const float4*)(W + (size_t)gm * K + k0 + kq);
            Ws[kq + 0][r] = v.x; Ws[kq + 1][r] = v.y;
            Ws[kq + 2][r] = v.z; Ws[kq + 3][r] = v.w;
        }
        __syncthreads();
        #pragma unroll
        for (int k = 0; k < GK; k++) {
            float a[8], b[4];
            *(float4*)(a)     = *(const float4*)&As[k][ty * 8];
            *(float4*)(a + 4) = *(const float4*)&As[k][ty * 8 + 4];
            *(float4*)(b)     = *(const float4*)&Ws[k][tx * 4];
            #pragma unroll
            for (int i = 0; i < 8; i++)
                #pragma unroll
                for (int j = 0; j < 4; j++)
                    acc[i][j] += a[i] * b[j];
        }
        __syncthreads();
    }

    #pragma unroll
    for (int i = 0; i < 8; i++) {
        int gr = row0 + ty * 8 + i;
        if (gr >= N) continue;
        #pragma unroll
        for (int j = 0; j < 4; j++) {
            int gm = col0 + tx * 4 + j;
            if (gm >= M) continue;
            float v = acc[i][j] + bias[gm];
            if (res)  v += res[(size_t)gr * M + gm];
            if (relu) v = fmaxf(v, 0.f);
            C[(size_t)gr * M + gm] = v;
        }
    }
}

// ---------------- LayerNorm: one row per block (128 threads) ----------------
__global__ __launch_bounds__(128)
void ln_kernel(const float* __restrict__ x, const float* __restrict__ sc,
               const float* __restrict__ bi, float* __restrict__ out) {
    const int row = blockIdx.x;
    const int t   = threadIdx.x;
    float v = x[row * H_DIM + t];

    __shared__ float sh1[4], sh2[4];
    float s = v;
    #pragma unroll
    for (int o = 16; o; o >>= 1) s += __shfl_xor_sync(0xffffffffu, s, o);
    if ((t & 31) == 0) sh1[t >> 5] = s;
    __syncthreads();
    float mean = (sh1[0] + sh1[1] + sh1[2] + sh1[3]) * (1.f / 128.f);

    float d = v - mean;
    float q = d * d;
    #pragma unroll
    for (int o = 16; o; o >>= 1) q += __shfl_xor_sync(0xffffffffu, q, o);
    if ((t & 31) == 0) sh2[t >> 5] = q;
    __syncthreads();
    float var = (sh2[0] + sh2[1] + sh2[2] + sh2[3]) * (1.f / 128.f);

    out[row * H_DIM + t] = d * rsqrtf(var + 1e-5f) * sc[t] + bi[t];
}

// ---------------- sparse attention: one thread per (query, head) ----------------
__global__ __launch_bounds__(256)
void attn_sparse_kernel(const float* __restrict__ qkv, float* __restrict__ o) {
    int gid = blockIdx.x * 256 + threadIdx.x;
    int q = gid >> 3;
    int h = gid & 7;
    if (q >= N_TOK) return;

    const float* qp = qkv + (size_t)q * 384 + h * HD;
    float4 q0 = *(const float4*)(qp);
    float4 q1 = *(const float4*)(qp + 4);
    float4 q2 = *(const float4*)(qp + 8);
    float4 q3 = *(const float4*)(qp + 12);

    int cnt = g_ncnt[q];
    const int* nb = &g_nbr[q * CAP];

    float m = -1e30f, l = 0.f;
    float acc[HD];
    #pragma unroll
    for (int d = 0; d < HD; d++) acc[d] = 0.f;

    for (int j = 0; j < cnt; j++) {
        int kidx = nb[j];
        const float* kp = qkv + (size_t)kidx * 384 + 128 + h * HD;
        float4 k0 = *(const float4*)(kp);
        float4 k1 = *(const float4*)(kp + 4);
        float4 k2 = *(const float4*)(kp + 8);
        float4 k3 = *(const float4*)(kp + 12);
        float s = q0.x * k0.x + q0.y * k0.y + q0.z * k0.z + q0.w * k0.w
                + q1.x * k1.x + q1.y * k1.y + q1.z * k1.z + q1.w * k1.w
                + q2.x * k2.x + q2.y * k2.y + q2.z * k2.z + q2.w * k2.w
                + q3.x * k3.x + q3.y * k3.y + q3.z * k3.z + q3.w * k3.w;
        s *= 0.25f;
        float mnew = fmaxf(m, s);
        float corr = __expf(m - mnew);
        float e    = __expf(s - mnew);
        l = l * corr + e;
        const float* vp = kp + 128;
        float4 v0 = *(const float4*)(vp);
        float4 v1 = *(const float4*)(vp + 4);
        float4 v2 = *(const float4*)(vp + 8);
        float4 v3 = *(const float4*)(vp + 12);
        acc[0]  = acc[0]  * corr + e * v0.x;  acc[1]  = acc[1]  * corr + e * v0.y;
        acc[2]  = acc[2]  * corr + e * v0.z;  acc[3]  = acc[3]  * corr + e * v0.w;
        acc[4]  = acc[4]  * corr + e * v1.x;  acc[5]  = acc[5]  * corr + e * v1.y;
        acc[6]  = acc[6]  * corr + e * v1.z;  acc[7]  = acc[7]  * corr + e * v1.w;
        acc[8]  = acc[8]  * corr + e * v2.x;  acc[9]  = acc[9]  * corr + e * v2.y;
        acc[10] = acc[10] * corr + e * v2.z;  acc[11] = acc[11] * corr + e * v2.w;
        acc[12] = acc[12] * corr + e * v3.x;  acc[13] = acc[13] * corr + e * v3.y;
        acc[14] = acc[14] * corr + e * v3.z;  acc[15] = acc[15] * corr + e * v3.w;
        m = mnew;
    }

    float inv = 1.f / l;
    float* op = o + (size_t)q * H_DIM + h * HD;
    #pragma unroll
    for (int d = 0; d < HD; d++) op[d] = acc[d] * inv;
}

// ---------------- heads epilogue ----------------
__global__ void final_kernel(float* __restrict__ out) {
    int i = blockIdx.x * blockDim.x + threadIdx.x;
    if (i >= N_TOK) return;
    float bb = 1.f / (1.f + __expf(-g_beta[i]));
    bb = fminf(fmaxf(bb, 1e-6f), 1.f - 1e-6f);
    out[i] = bb;
    float nn = 0.f;
    float lv[LAT_DIM];
    #pragma unroll
    for (int d = 0; d < LAT_DIM; d++) { lv[d] = g_lat[i * LAT_DIM + d]; nn += lv[d] * lv[d]; }
    float inv = 1.f / fmaxf(sqrtf(nn), 1e-12f);
    #pragma unroll
    for (int d = 0; d < LAT_DIM; d++) out[N_TOK + i * LAT_DIM + d] = lv[d] * inv;
}

// ---------------- host orchestration ----------------
extern "C" void kernel_launch(void* const* d_in, const int* in_sizes, int n_in,
                              void* d_out, int out_size) {
    const float* x_raw  = (const float*)d_in[0];
    const float* in_w   = (const float*)d_in[2];
    const float* in_b   = (const float*)d_in[3];
    const float* ln1_s  = (const float*)d_in[4];
    const float* ln1_b  = (const float*)d_in[5];
    const float* qkv_w  = (const float*)d_in[6];
    const float* qkv_b  = (const float*)d_in[7];
    const float* ao_w   = (const float*)d_in[8];
    const float* ao_b   = (const float*)d_in[9];
    const float* ln2_s  = (const float*)d_in[10];
    const float* ln2_b  = (const float*)d_in[11];
    const float* f1_w   = (const float*)d_in[12];
    const float* f1_b   = (const float*)d_in[13];
    const float* f2_w   = (const float*)d_in[14];
    const float* f2_b   = (const float*)d_in[15];
    const float* lat1_w = (const float*)d_in[16];
    const float* lat1_b = (const float*)d_in[17];
    const float* lat2_w = (const float*)d_in[18];
    const float* lat2_b = (const float*)d_in[19];
    const float* b1_w   = (const float*)d_in[20];
    const float* b1_b   = (const float*)d_in[21];
    const float* b2_w   = (const float*)d_in[22];
    const float* b2_b   = (const float*)d_in[23];

    float *x, *xn, *qkv, *attn, *tmp, *lat, *beta;
    cudaGetSymbolAddress((void**)&x,    g_x);
    cudaGetSymbolAddress((void**)&xn,   g_xn);
    cudaGetSymbolAddress((void**)&qkv,  g_qkv);
    cudaGetSymbolAddress((void**)&attn, g_attn);
    cudaGetSymbolAddress((void**)&tmp,  g_tmp);
    cudaGetSymbolAddress((void**)&lat,  g_lat);
    cudaGetSymbolAddress((void**)&beta, g_beta);

    dim3 blk(128);

    etaphi_kernel<<<(N_TOK + 255) / 256, 256>>>(x_raw);
    nbr_kernel<<<N_TOK / 8, 256>>>();

    // input projection: K=16, M=128
    gemm2_kernel<<<dim3(N_TOK / GM, (H_DIM + GN - 1) / GN), blk>>>(
        x_raw, in_w, in_b, nullptr, x, N_TOK, H_DIM, 16, 0);

    for (int l = 0; l < L_LAYER; l++) {
        ln_kernel<<<N_TOK, 128>>>(x, ln1_s + l * H_DIM, ln1_b + l * H_DIM, xn);
        gemm2_kernel<<<dim3(N_TOK / GM, (3 * H_DIM) / GN), blk>>>(
            xn, qkv_w + (size_t)l * 3 * H_DIM * H_DIM, qkv_b + l * 3 * H_DIM,
            nullptr, qkv, N_TOK, 3 * H_DIM, H_DIM, 0);
        attn_sparse_kernel<<<(N_TOK * NH) / 256, 256>>>(qkv, attn);
        gemm2_kernel<<<dim3(N_TOK / GM, H_DIM / GN), blk>>>(
            attn, ao_w + (size_t)l * H_DIM * H_DIM, ao_b + l * H_DIM,
            x, x, N_TOK, H_DIM, H_DIM, 0);
        ln_kernel<<<N_TOK, 128>>>(x, ln2_s + l * H_DIM, ln2_b + l * H_DIM, xn);
        gemm2_kernel<<<dim3(N_TOK / GM, FF_DIM / GN), blk>>>(
            xn, f1_w + (size_t)l * FF_DIM * H_DIM, f1_b + l * FF_DIM,
            nullptr, tmp, N_TOK, FF_DIM, H_DIM, 1);
        gemm2_kernel<<<dim3(N_TOK / GM, H_DIM / GN), blk>>>(
            tmp, f2_w + (size_t)l * H_DIM * FF_DIM, f2_b + l * H_DIM,
            x, x, N_TOK, H_DIM, FF_DIM, 0);
    }

    gemm2_kernel<<<dim3(N_TOK / GM, H_DIM / GN), blk>>>(
        x, lat1_w, lat1_b, nullptr, xn, N_TOK, H_DIM, H_DIM, 1);
    gemm2_kernel<<<dim3(N_TOK / GM, 1), blk>>>(
        xn, lat2_w, lat2_b, nullptr, lat, N_TOK, LAT_DIM, H_DIM, 0);

    gemm2_kernel<<<dim3(N_TOK / GM, 1), blk>>>(
        x, b1_w, b1_b, nullptr, tmp, N_TOK, H_DIM / 2, H_DIM, 1);
    gemm2_kernel<<<dim3(N_TOK / GM, 1), blk>>>(
        tmp, b2_w, b2_b, nullptr, beta, N_TOK, 1, H_DIM / 2, 0);

    final_kernel<<<(N_TOK + 255) / 256, 256>>>((float*)d_out);
}